// round 17
// baseline (speedup 1.0000x reference)
#include <cuda_runtime.h>
#include <cuda_fp16.h>
#include <cstdint>
#include <math.h>

// logits = x @ W^T + b ; softmax ; top-2 ; renormalize.
// R17: two-phase exact-rescue scheme (breaks the 13 cyc/MMA HMMA wall by
// issuing 3x fewer MMAs):
//   Phase 1: hh-only fp16 GEMM (single product) -> approx logits (err ~3e-4)
//            written to a device buffer. R16 pipeline structure, hi tiles only.
//   Phase 2: warp-per-token. Approx top-2; candidates within 6e-3 (~21 sigma)
//            of approx 2nd; exact fp32 dot for candidates only; exact top-2
//            indices + probs (softmax denom from approx logits — enters the
//            output only via the 1e-8 eps term).
// out[0:2T) = indices (as f32), out[2T:4T) = renormalized probs.

static constexpr int D_K  = 4096;
static constexpr int NE   = 128;
static constexpr int BM   = 128;
static constexpr int KC   = 64;
static constexpr int NCH  = D_K / KC;          // 64
static constexpr int RS   = 72;                // halves per smem row (64 + 8 pad)
static constexpr int HT   = 128 * RS * 2;      // 18432 B per (hi) tile
static constexpr int A_OFF = 0;                // A stages: [0, 36864)
static constexpr int B_OFF = 2 * HT;           // B stages: [36864, 73728)
static constexpr int MB_OFF = 4 * HT;          // 73728
static constexpr int SMEM_TOTAL = MB_OFF + 64;
static constexpr float WSCALE  = 64.0f;
static constexpr float IWSCALE = 1.0f / 64.0f;
static constexpr float MARGIN  = 6e-3f;

__device__ __half2 gWhi[NE * D_K / 2];
__device__ float   gLogits[16384 * NE];        // 8 MB scratch

__global__ void __launch_bounds__(256)
convW(const float* __restrict__ W)
{
    int i = blockIdx.x * 256 + threadIdx.x;
    float2 w = reinterpret_cast<const float2*>(W)[i];
    gWhi[i] = __floats2half2_rn(w.x * WSCALE, w.y * WSCALE);
}

__device__ __forceinline__ uint32_t smem_u32(const void* p) {
    uint32_t a;
    asm("{ .reg .u64 t; cvta.to.shared.u64 t, %1; cvt.u32.u64 %0, t; }" : "=r"(a) : "l"(p));
    return a;
}

#define LDM4(r, addr)                                                            \
    asm volatile("ldmatrix.sync.aligned.m8n8.x4.shared.b16 {%0,%1,%2,%3}, [%4];" \
                 : "=r"((r)[0]), "=r"((r)[1]), "=r"((r)[2]), "=r"((r)[3])        \
                 : "r"(addr))

#define MMA16816(c, a, b0, b1)                                               \
    asm volatile("mma.sync.aligned.m16n8k16.row.col.f32.f16.f16.f32 "        \
                 "{%0,%1,%2,%3}, {%4,%5,%6,%7}, {%8,%9}, {%0,%1,%2,%3};"     \
                 : "+f"((c)[0]), "+f"((c)[1]), "+f"((c)[2]), "+f"((c)[3])    \
                 : "r"((a)[0]), "r"((a)[1]), "r"((a)[2]), "r"((a)[3]),       \
                   "r"(b0), "r"(b1))

#define CP16(dst, src) \
    asm volatile("cp.async.cg.shared.global [%0], [%1], 16;" :: "r"(dst), "l"(src))

__device__ __forceinline__ void mbar_init(uint32_t a, uint32_t cnt) {
    asm volatile("mbarrier.init.shared.b64 [%0], %1;" :: "r"(a), "r"(cnt) : "memory");
}
__device__ __forceinline__ void mbar_arrive(uint32_t a) {
    asm volatile("mbarrier.arrive.release.cta.shared::cta.b64 _, [%0];" :: "r"(a) : "memory");
}
__device__ __forceinline__ void mbar_wait(uint32_t a, uint32_t parity) {
    asm volatile(
        "{\n\t.reg .pred P1;\n\t"
        "W%=:\n\t"
        "mbarrier.try_wait.parity.acquire.cta.shared::cta.b64 P1, [%0], %1, 0x989680;\n\t"
        "@P1 bra.uni DONE%=;\n\t"
        "bra.uni W%=;\n\t"
        "DONE%=:\n\t}"
        :: "r"(a), "r"(parity) : "memory");
}

// ============================ PHASE 1 ============================
__global__ void __launch_bounds__(384, 1)
router_p1(const float* __restrict__ x, const float* __restrict__ bias, int T)
{
    extern __shared__ char smem[];
    const uint32_t sbase = smem_u32(smem);
    const int tid  = threadIdx.x;
    const int wid  = tid >> 5, lane = tid & 31;
    const int t0   = blockIdx.x * BM;

    const uint32_t mFull0 = sbase + MB_OFF, mFull1 = mFull0 + 8;
    const uint32_t mEmp0  = mFull0 + 16,    mEmp1  = mFull0 + 24;
    if (tid == 0) {
        mbar_init(mFull0, 128); mbar_init(mFull1, 128);
        mbar_init(mEmp0, 256);  mbar_init(mEmp1, 256);
    }
    __syncthreads();

    if (wid >= 8) {
        // ================= PRODUCER (4 warps, 128 threads) =================
        const int ptid = tid - 256;
        const char* whiB = reinterpret_cast<const char*>(gWhi);

        float4 araw[16];
        auto fetchA = [&](int cc) {
            const int k0 = cc * KC;
#pragma unroll
            for (int j = 0; j < 16; j++) {
                int i = ptid + j * 128, row = i >> 4, c4 = i & 15;
                araw[j] = *reinterpret_cast<const float4*>(
                    x + (size_t)(t0 + row) * D_K + k0 + c4 * 4);
            }
        };
        auto stsA = [&](int st) {
            char* base = smem + A_OFF + st * HT;
#pragma unroll
            for (int j = 0; j < 16; j++) {
                int i = ptid + j * 128, row = i >> 4, c4 = i & 15;
                uint32_t off = (uint32_t)row * (RS * 2) + c4 * 8;
                uint2 hi;
                __half2 h0 = __floats2half2_rn(araw[j].x, araw[j].y);
                __half2 h1 = __floats2half2_rn(araw[j].z, araw[j].w);
                hi.x = *reinterpret_cast<uint32_t*>(&h0);
                hi.y = *reinterpret_cast<uint32_t*>(&h1);
                *reinterpret_cast<uint2*>(base + off) = hi;
            }
        };
        auto fillB = [&](int cc, int st) {
            const uint32_t sdst = sbase + B_OFF + st * HT;
            const int kByte = cc * KC * 2;
#pragma unroll
            for (int t = 0; t < 8; t++) {
                int i   = ptid + t * 128;
                int row = i >> 3, c16 = i & 7;
                uint32_t d = sdst + row * (RS * 2) + c16 * 16;
                size_t  go = (size_t)row * (D_K * 2) + kByte + c16 * 16;
                CP16(d, whiB + go);
            }
            asm volatile("cp.async.commit_group;" ::: "memory");
        };

        int pe[2] = {0, 0};
        fetchA(0);
        for (int c = 0; c < NCH; c++) {
            const int s = c & 1;
            const uint32_t mE = s ? mEmp1 : mEmp0;
            const uint32_t mF = s ? mFull1 : mFull0;
            if (c >= 2) { mbar_wait(mE, pe[s]); pe[s] ^= 1; }
            fillB(c, s);
            stsA(s);
            if (c + 1 < NCH) fetchA(c + 1);
            asm volatile("cp.async.wait_group 0;" ::: "memory");
            mbar_arrive(mF);
        }
        return;
    }

    // ================= CONSUMER (8 warps, 256 threads) =================
    const int wm = wid >> 2;     // 2 M-groups (64 tokens)
    const int wn = wid & 3;      // 4 N-groups (32 experts)

    float acc[4][4][4];          // [mt][n8][frag]
#pragma unroll
    for (int i = 0; i < 4; i++)
#pragma unroll
        for (int j = 0; j < 4; j++)
#pragma unroll
            for (int k = 0; k < 4; k++) acc[i][j][k] = 0.0f;

    const int ltile = lane >> 3, lr = lane & 7;
    const int lmoff = ((ltile & 1) * 8 + lr) * RS + (ltile >> 1) * 8;

    uint32_t Ah[2][4];           // double-buffered per (kk,mt) step
    uint32_t Bh[2][2][4];        // double-buffered per kk

    int cf[2] = {0, 0};
    for (int c = 0; c < NCH; c++) {
        const int s = c & 1;
        const uint32_t mF = s ? mFull1 : mFull0;
        const uint32_t mE = s ? mEmp1 : mEmp0;
        mbar_wait(mF, cf[s]); cf[s] ^= 1;

        const uint32_t aH = sbase + A_OFF + s * HT;
        const uint32_t bH = sbase + B_OFF + s * HT;

        {   // prologue: fragments for step 0
            uint32_t offA = (uint32_t)((wm * 64) * RS + lmoff) * 2;
            LDM4(Ah[0], aH + offA);
#pragma unroll
            for (int g = 0; g < 2; g++) {
                uint32_t offB = (uint32_t)((wn * 32 + g * 16) * RS + lmoff) * 2;
                LDM4(Bh[0][g], bH + offB);
            }
        }

#pragma unroll
        for (int st = 0; st < 16; st++) {      // st = kk*4 + mt
            const int kk = st >> 2, mt = st & 3;
            const int ab = st & 1;
            const int bb = kk & 1;

            if (mt < 3) {
                uint32_t offA = (uint32_t)((wm * 64 + (mt + 1) * 16) * RS
                                           + kk * 16 + lmoff) * 2;
                LDM4(Ah[ab ^ 1], aH + offA);
            } else if (kk < 3) {
                uint32_t offA = (uint32_t)((wm * 64) * RS + (kk + 1) * 16 + lmoff) * 2;
                LDM4(Ah[ab ^ 1], aH + offA);
#pragma unroll
                for (int g = 0; g < 2; g++) {
                    uint32_t offB = (uint32_t)((wn * 32 + g * 16) * RS
                                               + (kk + 1) * 16 + lmoff) * 2;
                    LDM4(Bh[bb ^ 1][g], bH + offB);
                }
            }

#pragma unroll
            for (int g = 0; g < 2; g++)
#pragma unroll
                for (int r = 0; r < 2; r++)
                    MMA16816(acc[mt][g * 2 + r], Ah[ab], Bh[bb][g][r], Bh[bb][g][r + 2]);
        }
        mbar_arrive(mE);
    }

    // ---- write approx logits (+bias, de-scale) straight to gmem ----
    const int lr4 = lane >> 2, lc2 = (lane & 3) * 2;
#pragma unroll
    for (int mt = 0; mt < 4; mt++)
#pragma unroll
        for (int nt = 0; nt < 4; nt++)
#pragma unroll
            for (int dr = 0; dr < 2; dr++) {
                int row = wm * 64 + mt * 16 + lr4 + dr * 8;
                int col = wn * 32 + nt * 8 + lc2;
                float2 v;
                v.x = acc[mt][nt][dr * 2 + 0] * IWSCALE + __ldg(&bias[col + 0]);
                v.y = acc[mt][nt][dr * 2 + 1] * IWSCALE + __ldg(&bias[col + 1]);
                *reinterpret_cast<float2*>(&gLogits[(size_t)(t0 + row) * NE + col]) = v;
            }
}

// ============================ PHASE 2 ============================
__global__ void __launch_bounds__(256)
router_p2(const float* __restrict__ x, const float* __restrict__ W,
          const float* __restrict__ bias, float* __restrict__ out, int T)
{
    const int lane = threadIdx.x & 31;
    const int t    = blockIdx.x * 8 + (threadIdx.x >> 5);
    if (t >= T) return;

    // approx logits: 4 per lane
    const float* lg = &gLogits[(size_t)t * NE];
    float v[4];
#pragma unroll
    for (int j = 0; j < 4; j++) v[j] = lg[lane * 4 + j];

    // warp top-2 approx VALUES
    float a1 = -INFINITY, a2 = -INFINITY;
#pragma unroll
    for (int j = 0; j < 4; j++) {
        float vv = v[j];
        if (vv > a1) { a2 = a1; a1 = vv; }
        else if (vv > a2) a2 = vv;
    }
#pragma unroll
    for (int off = 16; off; off >>= 1) {
        float o1 = __shfl_xor_sync(0xffffffffu, a1, off);
        float o2 = __shfl_xor_sync(0xffffffffu, a2, off);
        float b1 = fmaxf(a1, o1);
        float b2 = fmaxf(fminf(a1, o1), fmaxf(a2, o2));
        a1 = b1; a2 = b2;
    }
    const float thresh = a2 - MARGIN;

    // candidate indices (uniform across warp via ballot)
    int cand[8]; int nc = 0;
#pragma unroll
    for (int j = 0; j < 4; j++) {
        unsigned m = __ballot_sync(0xffffffffu, v[j] >= thresh);
        while (m && nc < 8) {
            int b = __ffs(m) - 1;
            m &= m - 1;
            cand[nc++] = b * 4 + j;
        }
    }

    // exact fp32 dots for candidates
    float acc[8];
    for (int c = 0; c < nc; c++) acc[c] = 0.0f;
    const float* xr = x + (size_t)t * D_K;
    for (int k = lane * 4; k < D_K; k += 128) {
        float4 xv = *reinterpret_cast<const float4*>(xr + k);
        for (int c = 0; c < nc; c++) {
            float4 wv = __ldg(reinterpret_cast<const float4*>(
                W + (size_t)cand[c] * D_K + k));
            acc[c] += xv.x * wv.x + xv.y * wv.y + xv.z * wv.z + xv.w * wv.w;
        }
    }
    for (int c = 0; c < nc; c++) {
#pragma unroll
        for (int off = 16; off; off >>= 1)
            acc[c] += __shfl_xor_sync(0xffffffffu, acc[c], off);
        acc[c] += __ldg(&bias[cand[c]]);
    }

    // softmax denominator from approx logits (max = a1)
    float s = 0.0f;
#pragma unroll
    for (int j = 0; j < 4; j++) s += __expf(v[j] - a1);
#pragma unroll
    for (int off = 16; off; off >>= 1)
        s += __shfl_xor_sync(0xffffffffu, s, off);

    // exact top-2 among candidates (ties -> lowest index, matching lax.top_k)
    float e1 = -INFINITY, e2 = -INFINITY;
    int   i1 = NE, i2 = NE;
    for (int c = 0; c < nc; c++) {
        float ev = acc[c]; int id = cand[c];
        if (ev > e1 || (ev == e1 && id < i1)) { e2 = e1; i2 = i1; e1 = ev; i1 = id; }
        else if (ev > e2 || (ev == e2 && id < i2)) { e2 = ev; i2 = id; }
    }

    if (lane == 0) {
        float p1 = __expf(e1 - a1) / s;
        float p2 = __expf(e2 - a1) / s;
        float den = p1 + p2 + 1e-8f;
        out[(size_t)t * 2 + 0] = (float)i1;
        out[(size_t)t * 2 + 1] = (float)i2;
        out[(size_t)2 * T + (size_t)t * 2 + 0] = p1 / den;
        out[(size_t)2 * T + (size_t)t * 2 + 1] = p2 / den;
    }
}

extern "C" void kernel_launch(void* const* d_in, const int* in_sizes, int n_in,
                              void* d_out, int out_size)
{
    const float* x = (const float*)d_in[0];
    const float* W = (const float*)d_in[1];
    const float* b = (const float*)d_in[2];
    float* out = (float*)d_out;

    int E = in_sizes[2];            // 128
    int D = in_sizes[1] / E;        // 4096
    int T = in_sizes[0] / D;        // 16384

    static int configured = -1;
    if (configured < 0) {
        cudaFuncSetAttribute(router_p1, cudaFuncAttributeMaxDynamicSharedMemorySize,
                             SMEM_TOTAL);
        configured = 1;
    }
    convW<<<(E * D / 2) / 256, 256>>>(W);
    router_p1<<<T / BM, 384, SMEM_TOTAL>>>(x, b, T);
    router_p2<<<T / 8, 256>>>(x, W, b, out, T);
}